// round 4
// baseline (speedup 1.0000x reference)
#include <cuda_runtime.h>
#include <math.h>

#define BMAX   4
#define NN     4096
#define DDIM   1024
#define MSPLIT 64
#define MCHUNK (NN / MSPLIT)    // 64
#define EPSV   1e-6f
#define ROWS_PER_BLOCK 16

// Scratch (device globals: no allocation allowed)
__device__ float g_part[BMAX][MSPLIT][3][DDIM]; // partial H0/Hc/Hs
__device__ float g_H[BMAX][3][DDIM];            // reduced H0/Hc/Hs
__device__ float g_CS[BMAX][2];                 // sum cos, sum sin
__device__ float g_cos[BMAX][NN];               // cos(phase)
__device__ float g_sin[BMAX][NN];               // sin(phase)
__device__ float g_coef[BMAX][NN];              // a*0.5 / max(rowsum, EPS)

// ---------------------------------------------------------------------------
// Kernel 0: per-batch trig arrays + sums. One block (1024 thr) per batch.
// ---------------------------------------------------------------------------
__global__ void kernel_cs(const float* __restrict__ phases) {
    __shared__ float sc[1024], ss[1024];
    const int b = blockIdx.x;
    const int t = threadIdx.x;
    float ac = 0.f, as = 0.f;
#pragma unroll
    for (int i = 0; i < NN / 1024; ++i) {
        int m = t + i * 1024;
        float p = phases[b * NN + m];
        float s = sinf(p), c = cosf(p);
        g_cos[b][m] = c;
        g_sin[b][m] = s;
        ac += c; as += s;
    }
    sc[t] = ac; ss[t] = as;
    __syncthreads();
    for (int off = 512; off > 0; off >>= 1) {
        if (t < off) { sc[t] += sc[t + off]; ss[t] += ss[t + off]; }
        __syncthreads();
    }
    if (t == 0) { g_CS[b][0] = sc[0]; g_CS[b][1] = ss[0]; }
}

// ---------------------------------------------------------------------------
// Kernel 1: per-row coefficient = a*0.5 / max(0.5*(N + cn*C + sn*S), EPS).
// grid (NN/256, B), 256 threads.
// ---------------------------------------------------------------------------
__global__ void kernel_coef(const float* __restrict__ alpha_p) {
    const int b = blockIdx.y;
    const int n = blockIdx.x * 256 + threadIdx.x;
    float a = fminf(fmaxf(alpha_p[0], 0.f), 1.f);
    float C = g_CS[b][0], S = g_CS[b][1];
    float cn = g_cos[b][n], sn = g_sin[b][n];
    float den = fmaxf(0.5f * ((float)NN + fmaf(cn, C, sn * S)), EPSV);
    g_coef[b][n] = a * 0.5f / den;
}

// ---------------------------------------------------------------------------
// Kernel 2: partial reductions of H0/Hc/Hs over 64-row m-chunks.
// grid = (MSPLIT, B), block = 256 threads, each thread owns 4 consecutive d.
// ---------------------------------------------------------------------------
__global__ void kernel_part(const float* __restrict__ hidden) {
    __shared__ float smc[MCHUNK], sms[MCHUNK];
    const int b  = blockIdx.y;
    const int ms = blockIdx.x;
    const int m0 = ms * MCHUNK;
    const int t  = threadIdx.x;

    if (t < MCHUNK) {
        smc[t] = g_cos[b][m0 + t];
        sms[t] = g_sin[b][m0 + t];
    }
    __syncthreads();

    const float4* hp = (const float4*)(hidden + ((size_t)b * NN + m0) * DDIM) + t;
    float4 a0 = make_float4(0.f, 0.f, 0.f, 0.f);
    float4 ac = a0, as = a0;

#pragma unroll 4
    for (int m = 0; m < MCHUNK; ++m) {
        float4 h = hp[(size_t)m * (DDIM / 4)];
        float c = smc[m], s = sms[m];
        a0.x += h.x;               a0.y += h.y;
        a0.z += h.z;               a0.w += h.w;
        ac.x = fmaf(c, h.x, ac.x); ac.y = fmaf(c, h.y, ac.y);
        ac.z = fmaf(c, h.z, ac.z); ac.w = fmaf(c, h.w, ac.w);
        as.x = fmaf(s, h.x, as.x); as.y = fmaf(s, h.y, as.y);
        as.z = fmaf(s, h.z, as.z); as.w = fmaf(s, h.w, as.w);
    }
    ((float4*)g_part[b][ms][0])[t] = a0;
    ((float4*)g_part[b][ms][1])[t] = ac;
    ((float4*)g_part[b][ms][2])[t] = as;
}

// ---------------------------------------------------------------------------
// Kernel 3: fold MSPLIT partials -> g_H. grid = (3, B), block = 256 (float4).
// ---------------------------------------------------------------------------
__global__ void kernel_reduce() {
    const int comp = blockIdx.x;
    const int b    = blockIdx.y;
    const int t    = threadIdx.x;
    float4 acc = make_float4(0.f, 0.f, 0.f, 0.f);
#pragma unroll 8
    for (int ms = 0; ms < MSPLIT; ++ms) {
        float4 v = ((const float4*)g_part[b][ms][comp])[t];
        acc.x += v.x; acc.y += v.y; acc.z += v.z; acc.w += v.w;
    }
    ((float4*)g_H[b][comp])[t] = acc;
}

// ---------------------------------------------------------------------------
// Kernel 4: output pass — pure FMA streaming.
// grid = (NN/ROWS_PER_BLOCK, B), block = 256, thread owns 4 consecutive d.
// ---------------------------------------------------------------------------
__global__ void kernel_out(const float* __restrict__ hidden,
                           const float* __restrict__ alpha_p,
                           float* __restrict__ out) {
    const int b  = blockIdx.y;
    const int n0 = blockIdx.x * ROWS_PER_BLOCK;
    const int t  = threadIdx.x;

    const float beta = 1.f - fminf(fmaxf(alpha_p[0], 0.f), 1.f);

    // per-thread slice of the H vectors (L2-broadcast across blocks)
    const float4 H0 = ((const float4*)g_H[b][0])[t];
    const float4 Hc = ((const float4*)g_H[b][1])[t];
    const float4 Hs = ((const float4*)g_H[b][2])[t];

    const float4* hv = (const float4*)(hidden + ((size_t)b * NN + n0) * DDIM) + t;
    float4*       ov = (float4*)(out + ((size_t)b * NN + n0) * DDIM) + t;

#pragma unroll 4
    for (int r = 0; r < ROWS_PER_BLOCK; ++r) {
        int n = n0 + r;
        float cn = g_cos[b][n];
        float sn = g_sin[b][n];
        float cf = g_coef[b][n];

        float4 h = hv[(size_t)r * (DDIM / 4)];
        float4 o;
        o.x = fmaf(cf, fmaf(sn, Hs.x, fmaf(cn, Hc.x, H0.x)), beta * h.x);
        o.y = fmaf(cf, fmaf(sn, Hs.y, fmaf(cn, Hc.y, H0.y)), beta * h.y);
        o.z = fmaf(cf, fmaf(sn, Hs.z, fmaf(cn, Hc.z, H0.z)), beta * h.z);
        o.w = fmaf(cf, fmaf(sn, Hs.w, fmaf(cn, Hc.w, H0.w)), beta * h.w);
        ov[(size_t)r * (DDIM / 4)] = o;
    }
}

// ---------------------------------------------------------------------------
// Launch
// ---------------------------------------------------------------------------
extern "C" void kernel_launch(void* const* d_in, const int* in_sizes, int n_in,
                              void* d_out, int out_size) {
    const float* hidden = (const float*)d_in[0];
    const float* phases = (const float*)d_in[1];
    const float* alpha  = (const float*)d_in[2];
    float* out = (float*)d_out;

    const int B = in_sizes[1] / NN;

    kernel_cs<<<B, 1024>>>(phases);
    kernel_part<<<dim3(MSPLIT, B), 256>>>(hidden);
    kernel_reduce<<<dim3(3, B), 256>>>();
    kernel_coef<<<dim3(NN / 256, B), 256>>>(alpha);
    kernel_out<<<dim3(NN / ROWS_PER_BLOCK, B), 256>>>(hidden, alpha, out);
}

// round 6
// speedup vs baseline: 1.2021x; 1.2021x over previous
#include <cuda_runtime.h>
#include <math.h>

#define BMAX   4
#define NN     4096
#define DDIM   1024
#define MSPLIT 128
#define MCHUNK (NN / MSPLIT)    // 32
#define EPSV   1e-6f
#define ROWS_PER_BLOCK 32

// Scratch (device globals: no allocation allowed)
__device__ float g_part[BMAX][MSPLIT][3][DDIM]; // partial H0/Hc/Hs (6 MB)
__device__ float g_csp[BMAX][MSPLIT][2];        // partial sum cos / sum sin
__device__ float g_H[BMAX][3][DDIM];            // reduced H0/Hc/Hs
__device__ float g_CS[BMAX][2];                 // final sum cos, sum sin

// ---------------------------------------------------------------------------
// Kernel 1: partial reductions of H0/Hc/Hs over 32-row m-chunks.
// grid = (MSPLIT, B) = 512 blocks, 256 threads, thread owns 4 consecutive d.
// Each block computes sincos for its own 32 rows (32 threads, once).
// ---------------------------------------------------------------------------
__global__ void kernel_part(const float* __restrict__ hidden,
                            const float* __restrict__ phases) {
    __shared__ float smc[MCHUNK], sms[MCHUNK];
    const int b  = blockIdx.y;
    const int ms = blockIdx.x;
    const int m0 = ms * MCHUNK;
    const int t  = threadIdx.x;

    if (t < MCHUNK) {
        float p = phases[b * NN + m0 + t];
        float s, c;
        sincosf(p, &s, &c);
        smc[t] = c;
        sms[t] = s;
        // warp-reduce the 32 trig values -> per-block partial C/S
        float rc = c, rs = s;
#pragma unroll
        for (int off = 16; off > 0; off >>= 1) {
            rc += __shfl_xor_sync(0xffffffffu, rc, off);
            rs += __shfl_xor_sync(0xffffffffu, rs, off);
        }
        if (t == 0) { g_csp[b][ms][0] = rc; g_csp[b][ms][1] = rs; }
    }
    __syncthreads();

    const float4* hp = (const float4*)(hidden + ((size_t)b * NN + m0) * DDIM) + t;
    float4 a0 = make_float4(0.f, 0.f, 0.f, 0.f);
    float4 ac = a0, as = a0;

#pragma unroll 8
    for (int m = 0; m < MCHUNK; ++m) {
        float4 h = hp[(size_t)m * (DDIM / 4)];
        float c = smc[m], s = sms[m];
        a0.x += h.x;               a0.y += h.y;
        a0.z += h.z;               a0.w += h.w;
        ac.x = fmaf(c, h.x, ac.x); ac.y = fmaf(c, h.y, ac.y);
        ac.z = fmaf(c, h.z, ac.z); ac.w = fmaf(c, h.w, ac.w);
        as.x = fmaf(s, h.x, as.x); as.y = fmaf(s, h.y, as.y);
        as.z = fmaf(s, h.z, as.z); as.w = fmaf(s, h.w, as.w);
    }
    ((float4*)g_part[b][ms][0])[t] = a0;
    ((float4*)g_part[b][ms][1])[t] = ac;
    ((float4*)g_part[b][ms][2])[t] = as;
}

// ---------------------------------------------------------------------------
// Kernel 2: fold MSPLIT partials -> g_H; block (0,b) also folds C/S.
// grid = (3, B) = 12 blocks, 256 threads (float4 per thread).
// ---------------------------------------------------------------------------
__global__ void kernel_reduce() {
    const int comp = blockIdx.x;
    const int b    = blockIdx.y;
    const int t    = threadIdx.x;

    if (comp == 0 && t < 64) {
        // fold 128 partial C and 128 partial S with 64 threads:
        // t<32 -> C lanes, t>=32 -> S lanes (each lane folds 4 chunks)
        int which = t >> 5;           // 0 = cos, 1 = sin
        int lane  = t & 31;
        float v = 0.f;
#pragma unroll
        for (int i = 0; i < 4; ++i)
            v += g_csp[b][lane + i * 32][which];
#pragma unroll
        for (int off = 16; off > 0; off >>= 1)
            v += __shfl_xor_sync(0xffffffffu, v, off, 32);
        if (lane == 0) g_CS[b][which] = v;
    }

    float4 acc = make_float4(0.f, 0.f, 0.f, 0.f);
#pragma unroll 8
    for (int ms = 0; ms < MSPLIT; ++ms) {
        float4 v = ((const float4*)g_part[b][ms][comp])[t];
        acc.x += v.x; acc.y += v.y; acc.z += v.z; acc.w += v.w;
    }
    ((float4*)g_H[b][comp])[t] = acc;
}

// ---------------------------------------------------------------------------
// Kernel 3: output pass — per-block row trig+division (32 threads, once),
// then pure FMA/float4 streaming.
// grid = (NN/ROWS_PER_BLOCK, B) = 512 blocks, 256 threads.
// ---------------------------------------------------------------------------
__global__ void kernel_out(const float* __restrict__ hidden,
                           const float* __restrict__ phases,
                           const float* __restrict__ alpha_p,
                           float* __restrict__ out) {
    __shared__ float scn[ROWS_PER_BLOCK], ssn[ROWS_PER_BLOCK], scf[ROWS_PER_BLOCK];
    const int b  = blockIdx.y;
    const int n0 = blockIdx.x * ROWS_PER_BLOCK;
    const int t  = threadIdx.x;

    const float a    = fminf(fmaxf(alpha_p[0], 0.f), 1.f);
    const float beta = 1.f - a;

    if (t < ROWS_PER_BLOCK) {
        float p = phases[b * NN + n0 + t];
        float sn, cn;
        sincosf(p, &sn, &cn);
        float C = g_CS[b][0], S = g_CS[b][1];
        float den = fmaxf(0.5f * ((float)NN + fmaf(cn, C, sn * S)), EPSV);
        scn[t] = cn;
        ssn[t] = sn;
        scf[t] = a * 0.5f / den;
    }
    __syncthreads();

    // per-thread slice of the H vectors (L2-broadcast across blocks)
    const float4 H0 = ((const float4*)g_H[b][0])[t];
    const float4 Hc = ((const float4*)g_H[b][1])[t];
    const float4 Hs = ((const float4*)g_H[b][2])[t];

    const float4* hv = (const float4*)(hidden + ((size_t)b * NN + n0) * DDIM) + t;
    float4*       ov = (float4*)(out + ((size_t)b * NN + n0) * DDIM) + t;

#pragma unroll 8
    for (int r = 0; r < ROWS_PER_BLOCK; ++r) {
        float cn = scn[r];
        float sn = ssn[r];
        float cf = scf[r];

        float4 h = hv[(size_t)r * (DDIM / 4)];
        float4 o;
        o.x = fmaf(cf, fmaf(sn, Hs.x, fmaf(cn, Hc.x, H0.x)), beta * h.x);
        o.y = fmaf(cf, fmaf(sn, Hs.y, fmaf(cn, Hc.y, H0.y)), beta * h.y);
        o.z = fmaf(cf, fmaf(sn, Hs.z, fmaf(cn, Hc.z, H0.z)), beta * h.z);
        o.w = fmaf(cf, fmaf(sn, Hs.w, fmaf(cn, Hc.w, H0.w)), beta * h.w);
        ov[(size_t)r * (DDIM / 4)] = o;
    }
}

// ---------------------------------------------------------------------------
// Launch — exactly 3 kernels.
// ---------------------------------------------------------------------------
extern "C" void kernel_launch(void* const* d_in, const int* in_sizes, int n_in,
                              void* d_out, int out_size) {
    const float* hidden = (const float*)d_in[0];
    const float* phases = (const float*)d_in[1];
    const float* alpha  = (const float*)d_in[2];
    float* out = (float*)d_out;

    const int B = in_sizes[1] / NN;

    kernel_part<<<dim3(MSPLIT, B), 256>>>(hidden, phases);
    kernel_reduce<<<dim3(3, B), 256>>>();
    kernel_out<<<dim3(NN / ROWS_PER_BLOCK, B), 256>>>(hidden, phases, alpha, out);
}